// round 1
// baseline (speedup 1.0000x reference)
#include <cuda_runtime.h>
#include <cuda_bf16.h>
#include <math.h>

// Problem constants (fixed by the dataset)
#define NN 32768
#define EE 262144
#define GG 64
#define HH 128
#define PER_ (NN/GG)

// ---------------- scratch (device globals; no allocation allowed) -------------
__device__ float g_C[HH*HH];          // W_ee @ M0c
__device__ float g_cvec[HH];          // b_ee @ M0c
__device__ float g_GD[GG*HH];         // graph_fts @ M0d
__device__ float g_zD[NN*HH];
__device__ float g_zS[NN*HH];
__device__ float g_e0[(size_t)EE*HH];
__device__ float g_e1[(size_t)EE*HH];
__device__ unsigned g_aggenc[NN*HH];
__device__ float g_agg[NN*HH];
__device__ float g_t1[NN*HH];
__device__ float g_h1[NN*HH];
__device__ float g_qkv[NN*3*HH];
__device__ float g_o[NN*HH];
__device__ float g_t2[NN*HH];
__device__ float g_h2[NN*HH];
__device__ float g_out[NN*HH];
__device__ float g_mlp1[NN*2*HH];
__device__ float g_out2[NN*HH];
__device__ float g_part[256*256];
__device__ float g_stats[256];

// ---------------- helpers ----------------------------------------------------
__device__ __forceinline__ float leaky_f(float v) { return v > 0.0f ? v : 0.01f*v; }

__device__ __forceinline__ float fast_exp(float x) {
    // exp(x) for x <= 0 (clamped); ~2e-7 rel err, pure FFMA (no MUFU)
    x = fmaxf(x, -87.0f);
    float t  = x * 1.4426950408889634f;
    float fl = floorf(t);
    float f  = t - fl;
    float p  =            1.339077600e-4f;
    p = p * f + 9.618437357e-4f;
    p = p * f + 9.556031144e-3f;
    p = p * f + 5.550332471e-2f;
    p = p * f + 2.402264923e-1f;
    p = p * f + 6.931471825e-1f;
    p = p * f + 1.0f;
    int ei = (int)fl;
    return __int_as_float((ei + 127) << 23) * p;
}

__device__ __forceinline__ unsigned enc_f(float f) {
    unsigned u = __float_as_uint(f);
    return (u & 0x80000000u) ? ~u : (u | 0x80000000u);
}
__device__ __forceinline__ float dec_f(unsigned u) {
    return (u & 0x80000000u) ? __uint_as_float(u ^ 0x80000000u) : __uint_as_float(~u);
}
#define ENC_NEGINF 0x007FFFFFu   // enc(-inf)

// ---------------- generic fp32 tiled GEMM ------------------------------------
// C[M,N] = epilogue( (PRE_LEAKY? leaky(A) : A)[M,K] @ B[K,N] )
// epilogue: (+ C if ACCUM) (+ bias[col] if BIAS) (+ resid[r,c] if RESID) (act)
#define BM 64
#define BN 64
#define BKK 16

template<bool PRE_LEAKY, int OUT_ACT, bool BIAS, bool ACCUM, bool RESID>
__global__ void __launch_bounds__(256) gemm_k(
    const float* __restrict__ A, const float* __restrict__ B,
    float* __restrict__ C, const float* __restrict__ bias,
    const float* __restrict__ resid, int M, int N, int K)
{
    __shared__ float As[BKK][BM+1];
    __shared__ float Bs[BKK][BN];
    int row0 = blockIdx.y * BM;
    int col0 = blockIdx.x * BN;
    int tid = threadIdx.x;
    int tx = tid & 15, ty = tid >> 4;
    float acc[4][4] = {};

    for (int k0 = 0; k0 < K; k0 += BKK) {
        #pragma unroll
        for (int i = 0; i < 4; i++) {
            int e = tid + i*256;
            int m = e >> 4, kk = e & 15;
            float v = A[(size_t)(row0 + m)*K + k0 + kk];
            if (PRE_LEAKY) v = leaky_f(v);
            As[kk][m] = v;
        }
        #pragma unroll
        for (int i = 0; i < 4; i++) {
            int e = tid + i*256;
            int kk = e >> 6, n = e & 63;
            Bs[kk][n] = B[(size_t)(k0 + kk)*N + col0 + n];
        }
        __syncthreads();
        #pragma unroll
        for (int kk = 0; kk < BKK; kk++) {
            float a[4], b[4];
            #pragma unroll
            for (int i = 0; i < 4; i++) a[i] = As[kk][ty*4 + i];
            #pragma unroll
            for (int j = 0; j < 4; j++) b[j] = Bs[kk][tx*4 + j];
            #pragma unroll
            for (int i = 0; i < 4; i++)
                #pragma unroll
                for (int j = 0; j < 4; j++)
                    acc[i][j] += a[i]*b[j];
        }
        __syncthreads();
    }
    #pragma unroll
    for (int i = 0; i < 4; i++) {
        int r = row0 + ty*4 + i;
        #pragma unroll
        for (int j = 0; j < 4; j++) {
            int c = col0 + tx*4 + j;
            size_t idx = (size_t)r*N + c;
            float v = acc[i][j];
            if (ACCUM) v += C[idx];
            if (BIAS)  v += bias[c];
            if (RESID) v += resid[idx];
            if (OUT_ACT == 1) v = fmaxf(v, 0.0f);
            else if (OUT_ACT == 2) v = leaky_f(v);
            C[idx] = v;
        }
    }
}

// ---------------- small kernels ----------------------------------------------
__global__ void cvec_k(const float* __restrict__ b_ee, const float* __restrict__ M0) {
    int j = threadIdx.x;
    float s = 0.0f;
    for (int t = 0; t < HH; t++) s += b_ee[t] * M0[(size_t)(4*HH + t)*HH + j];
    g_cvec[j] = s;
}

__global__ void edge_gather_add_k(const int* __restrict__ src, const int* __restrict__ dst,
                                  const int* __restrict__ batch, int E)
{
    int idx = blockIdx.x*blockDim.x + threadIdx.x;
    int e = idx >> 5; int c4 = idx & 31;
    if (e >= E) return;
    int s = src[e], d = dst[e];
    int g = batch[d];
    float4* m0 = (float4*)g_e0;
    const float4* zD = (const float4*)g_zD;
    const float4* zS = (const float4*)g_zS;
    const float4* GD = (const float4*)g_GD;
    const float4* cv = (const float4*)g_cvec;
    float4 v = m0[(size_t)e*32 + c4];
    float4 a = zD[(size_t)d*32 + c4];
    float4 b = zS[(size_t)s*32 + c4];
    float4 c = GD[(size_t)g*32 + c4];
    float4 k = cv[c4];
    v.x += a.x + b.x + c.x + k.x;
    v.y += a.y + b.y + c.y + k.y;
    v.z += a.z + b.z + c.z + k.z;
    v.w += a.w + b.w + c.w + k.w;
    m0[(size_t)e*32 + c4] = v;
}

__global__ void agg_init_k(int total) {
    int i = blockIdx.x*blockDim.x + threadIdx.x;
    if (i < total) g_aggenc[i] = ENC_NEGINF;
}

__global__ void seg_max_k(const float* __restrict__ m3, const int* __restrict__ dst, int E) {
    int idx = blockIdx.x*blockDim.x + threadIdx.x;
    int e = idx >> 7; int c = idx & 127;
    if (e >= E) return;
    float v = m3[(size_t)e*HH + c];
    atomicMax(&g_aggenc[dst[e]*HH + c], enc_f(v));
}

__global__ void agg_decode_k(int total) {
    int i = blockIdx.x*blockDim.x + threadIdx.x;
    if (i >= total) return;
    float f = dec_f(g_aggenc[i]);
    if (!isfinite(f)) f = 0.0f;
    g_agg[i] = f;
}

// attention: one block per (graph, head); blockDim = PER (512); flash-style
__global__ void __launch_bounds__(512) attn_k(const float* __restrict__ qkv,
                                              float* __restrict__ o, int PER)
{
    __shared__ float Ks[128][32];
    __shared__ float Vs[128][32];
    int g = blockIdx.x, h = blockIdx.y;
    int tid = threadIdx.x;
    int n = g*PER + tid;
    const float scale = 0.17677669529663687f; // 1/sqrt(32)
    float q[32];
    #pragma unroll
    for (int d = 0; d < 32; d++)
        q[d] = qkv[(size_t)n*384 + h*32 + d] * scale;

    float m = -INFINITY, l = 0.0f;
    float acc[32];
    #pragma unroll
    for (int d = 0; d < 32; d++) acc[d] = 0.0f;

    for (int c0 = 0; c0 < PER; c0 += 128) {
        __syncthreads();
        for (int i = tid; i < 128*32; i += 512) {
            int r = i >> 5, d = i & 31;
            size_t base = (size_t)(g*PER + c0 + r)*384 + h*32 + d;
            Ks[r][d] = qkv[base + 128];
            Vs[r][d] = qkv[base + 256];
        }
        __syncthreads();
        for (int j = 0; j < 128; j++) {
            float s = 0.0f;
            #pragma unroll
            for (int d = 0; d < 32; d++) s += q[d]*Ks[j][d];
            float mn = fmaxf(m, s);
            float a = fast_exp(m - mn);
            float p = fast_exp(s - mn);
            l = l*a + p;
            #pragma unroll
            for (int d = 0; d < 32; d++) acc[d] = acc[d]*a + p*Vs[j][d];
            m = mn;
        }
    }
    float inv = 1.0f / l;
    #pragma unroll
    for (int d = 0; d < 32; d++)
        o[(size_t)n*HH + h*32 + d] = acc[d]*inv;
}

// BN: deterministic two-stage column stats
__global__ void bn_stats1_k(const float* __restrict__ x, int rowsPer) {
    int c = threadIdx.x;      // 128
    int b = blockIdx.x;       // 256
    size_t r0 = (size_t)b * rowsPer;
    float s = 0.0f, s2 = 0.0f;
    for (int r = 0; r < rowsPer; r++) {
        float v = x[(r0 + r)*HH + c];
        s += v; s2 += v*v;
    }
    g_part[b*256 + c] = s;
    g_part[b*256 + 128 + c] = s2;
}
__global__ void bn_stats2_k(int nb, float invN) {
    int c = threadIdx.x;
    float s = 0.0f, s2 = 0.0f;
    for (int b = 0; b < nb; b++) { s += g_part[b*256 + c]; s2 += g_part[b*256 + 128 + c]; }
    float mu = s * invN;
    float var = s2 * invN - mu*mu;
    g_stats[c] = mu;
    g_stats[128 + c] = rsqrtf(var + 1e-5f);
}
__global__ void bn_apply_k(const float* __restrict__ x, const float* __restrict__ w,
                           const float* __restrict__ b, float* __restrict__ y, int total)
{
    int i = blockIdx.x*blockDim.x + threadIdx.x;
    if (i >= total) return;
    int c = i & 127;
    y[i] = (x[i] - g_stats[c]) * g_stats[128 + c] * w[c] + b[c];
}

__global__ void add_k(const float* __restrict__ a, const float* __restrict__ b,
                      float* __restrict__ y, int total)
{
    int i = blockIdx.x*blockDim.x + threadIdx.x;
    if (i < total) y[i] = a[i] + b[i];
}

// ---------------- host orchestration -----------------------------------------
static inline void launch_gemm_plain(const float* A, const float* B, float* C, int M, int N, int K) {
    dim3 grid(N/BN, M/BM);
    gemm_k<false,0,false,false,false><<<grid,256>>>(A,B,C,nullptr,nullptr,M,N,K);
}
static inline void launch_gemm_accum(const float* A, const float* B, float* C, int M, int N, int K) {
    dim3 grid(N/BN, M/BM);
    gemm_k<false,0,false,true,false><<<grid,256>>>(A,B,C,nullptr,nullptr,M,N,K);
}
static inline void launch_gemm_accum_resid(const float* A, const float* B, float* C,
                                           const float* resid, int M, int N, int K) {
    dim3 grid(N/BN, M/BM);
    gemm_k<false,0,false,true,true><<<grid,256>>>(A,B,C,nullptr,resid,M,N,K);
}
static inline void launch_gemm_preleaky(const float* A, const float* B, float* C, int M, int N, int K) {
    dim3 grid(N/BN, M/BM);
    gemm_k<true,0,false,false,false><<<grid,256>>>(A,B,C,nullptr,nullptr,M,N,K);
}
static inline void launch_gemm_bias(const float* A, const float* B, float* C,
                                    const float* bias, int M, int N, int K) {
    dim3 grid(N/BN, M/BM);
    gemm_k<false,0,true,false,false><<<grid,256>>>(A,B,C,bias,nullptr,M,N,K);
}
static inline void launch_gemm_bias_resid(const float* A, const float* B, float* C,
                                          const float* bias, const float* resid, int M, int N, int K) {
    dim3 grid(N/BN, M/BM);
    gemm_k<false,0,true,false,true><<<grid,256>>>(A,B,C,bias,resid,M,N,K);
}
static inline void launch_gemm_bias_relu(const float* A, const float* B, float* C,
                                         const float* bias, int M, int N, int K) {
    dim3 grid(N/BN, M/BM);
    gemm_k<false,1,true,false,false><<<grid,256>>>(A,B,C,bias,nullptr,M,N,K);
}

extern "C" void kernel_launch(void* const* d_in, const int* in_sizes, int n_in,
                              void* d_out, int out_size)
{
    const float* node_fts  = (const float*)d_in[0];
    const float* edge_attr = (const float*)d_in[1];
    const float* graph_fts = (const float*)d_in[2];
    const float* hidden    = (const float*)d_in[3];
    const float* W_ee      = (const float*)d_in[4];
    const float* b_ee      = (const float*)d_in[5];
    const float* M0        = (const float*)d_in[6];
    const float* M1        = (const float*)d_in[7];
    const float* M2        = (const float*)d_in[8];
    const float* M3        = (const float*)d_in[9];
    const float* U1        = (const float*)d_in[10];
    const float* U2        = (const float*)d_in[11];
    const float* Wqkv      = (const float*)d_in[12];
    const float* bqkv      = (const float*)d_in[13];
    const float* Wo        = (const float*)d_in[14];
    const float* bo        = (const float*)d_in[15];
    const float* bn1_w     = (const float*)d_in[16];
    const float* bn1_b     = (const float*)d_in[17];
    const float* bn2_w     = (const float*)d_in[18];
    const float* bn2_b     = (const float*)d_in[19];
    const float* bn3_w     = (const float*)d_in[20];
    const float* bn3_b     = (const float*)d_in[21];
    const float* W1        = (const float*)d_in[22];
    const float* b1        = (const float*)d_in[23];
    const float* W2        = (const float*)d_in[24];
    const float* b2        = (const float*)d_in[25];
    const int*   edge_index= (const int*)d_in[26];
    const int*   batch     = (const int*)d_in[27];

    const int N = in_sizes[0] / HH;
    const int E = in_sizes[1] / HH;
    const int G = in_sizes[2] / HH;
    const int PER = N / G;
    const int* src = edge_index;
    const int* dst = edge_index + E;
    float* outp = (float*)d_out;

    // device-global pointers (host-side addresses of device symbols work with <<< >>> args
    // only via cudaGetSymbolAddress; simpler: kernels reference globals directly, but GEMM
    // takes pointers — fetch symbol addresses once per call (cheap host ops, not captured)
    float *pC, *pGD, *pzD, *pzS, *pe0, *pe1, *pagg, *pt1, *ph1, *pqkv, *po, *pt2, *ph2, *pout, *pmlp1, *pout2, *pcvec;
    cudaGetSymbolAddress((void**)&pC,    g_C);
    cudaGetSymbolAddress((void**)&pGD,   g_GD);
    cudaGetSymbolAddress((void**)&pzD,   g_zD);
    cudaGetSymbolAddress((void**)&pzS,   g_zS);
    cudaGetSymbolAddress((void**)&pe0,   g_e0);
    cudaGetSymbolAddress((void**)&pe1,   g_e1);
    cudaGetSymbolAddress((void**)&pagg,  g_agg);
    cudaGetSymbolAddress((void**)&pt1,   g_t1);
    cudaGetSymbolAddress((void**)&ph1,   g_h1);
    cudaGetSymbolAddress((void**)&pqkv,  g_qkv);
    cudaGetSymbolAddress((void**)&po,    g_o);
    cudaGetSymbolAddress((void**)&pt2,   g_t2);
    cudaGetSymbolAddress((void**)&ph2,   g_h2);
    cudaGetSymbolAddress((void**)&pout,  g_out);
    cudaGetSymbolAddress((void**)&pmlp1, g_mlp1);
    cudaGetSymbolAddress((void**)&pout2, g_out2);
    cudaGetSymbolAddress((void**)&pcvec, g_cvec);

    // ---- tiny precomputes -------------------------------------------------
    // C = W_ee @ M0[4H:5H]   (128x128x128)
    launch_gemm_plain(W_ee, M0 + (size_t)4*HH*HH, pC, HH, HH, HH);
    cvec_k<<<1, HH>>>(b_ee, M0);
    // GD = graph_fts @ M0[5H:6H]  (64x128x128)
    launch_gemm_plain(graph_fts, M0 + (size_t)5*HH*HH, pGD, G, HH, HH);

    // ---- node-side M0 folds ----------------------------------------------
    launch_gemm_plain(node_fts, M0,                      pzD, N, HH, HH);
    launch_gemm_accum(hidden,   M0 + (size_t)1*HH*HH,    pzD, N, HH, HH);
    launch_gemm_plain(node_fts, M0 + (size_t)2*HH*HH,    pzS, N, HH, HH);
    launch_gemm_accum(hidden,   M0 + (size_t)3*HH*HH,    pzS, N, HH, HH);

    // ---- edge pipeline ----------------------------------------------------
    launch_gemm_plain(edge_attr, pC, pe0, E, HH, HH);                 // ea@M0c (folded)
    {
        int total = E*32;
        edge_gather_add_k<<<(total + 255)/256, 256>>>(src, dst, batch, E);
    }
    launch_gemm_preleaky(pe0, M1, pe1, E, HH, HH);
    launch_gemm_preleaky(pe1, M2, pe0, E, HH, HH);
    launch_gemm_preleaky(pe0, M3, pe1, E, HH, HH);

    // ---- segment max ------------------------------------------------------
    {
        int total = N*HH;
        agg_init_k<<<(total + 255)/256, 256>>>(total);
        int et = E*HH;
        seg_max_k<<<(et + 255)/256, 256>>>(pe1, dst, E);
        agg_decode_k<<<(total + 255)/256, 256>>>(total);
    }

    // ---- h1 = BN1(h_local + node_fts) ------------------------------------
    launch_gemm_plain(node_fts, U1,                    pt1, N, HH, HH);
    launch_gemm_accum(hidden,   U1 + (size_t)HH*HH,    pt1, N, HH, HH);
    launch_gemm_accum_resid(pagg, U2, pt1, node_fts, N, HH, HH);
    {
        int rowsPer = N/256;
        bn_stats1_k<<<256, 128>>>(pt1, rowsPer);
        bn_stats2_k<<<1, 128>>>(256, 1.0f/(float)N);
        int total = N*HH;
        bn_apply_k<<<(total + 255)/256, 256>>>(pt1, bn1_w, bn1_b, ph1, total);
    }

    // ---- attention --------------------------------------------------------
    launch_gemm_bias(node_fts, Wqkv, pqkv, bqkv, N, 3*HH, HH);
    attn_k<<<dim3(G, 4), PER>>>(pqkv, po, PER);
    launch_gemm_bias_resid(po, Wo, pt2, bo, node_fts, N, HH, HH);
    {
        int rowsPer = N/256;
        bn_stats1_k<<<256, 128>>>(pt2, rowsPer);
        bn_stats2_k<<<1, 128>>>(256, 1.0f/(float)N);
        int total = N*HH;
        bn_apply_k<<<(total + 255)/256, 256>>>(pt2, bn2_w, bn2_b, ph2, total);
    }

    // ---- combine + MLP ----------------------------------------------------
    {
        int total = N*HH;
        add_k<<<(total + 255)/256, 256>>>(ph1, ph2, pout, total);
    }
    launch_gemm_bias_relu(pout, W1, pmlp1, b1, N, 2*HH, HH);
    launch_gemm_bias_resid(pmlp1, W2, pout2, b2, pout, N, HH, 2*HH);

    // ---- BN3 -> output ----------------------------------------------------
    {
        int rowsPer = N/256;
        bn_stats1_k<<<256, 128>>>(pout2, rowsPer);
        bn_stats2_k<<<1, 128>>>(256, 1.0f/(float)N);
        int total = N*HH;
        bn_apply_k<<<(total + 255)/256, 256>>>(pout2, bn3_w, bn3_b, outp, total);
    }
}

// round 4
// speedup vs baseline: 1.2503x; 1.2503x over previous
#include <cuda_runtime.h>
#include <cuda_bf16.h>
#include <math.h>
#include <stdint.h>

// Problem constants
#define NN 32768
#define EE 262144
#define GG 64
#define HH 128

// ---------------- scratch ----------------------------------------------------
__device__ float g_C[HH*HH];
__device__ float g_cvec[HH];
__device__ float g_GD[GG*HH];
__device__ float g_zD[NN*HH];
__device__ float g_zS[NN*HH];
__device__ float g_e0[(size_t)EE*HH];
__device__ float g_e1[(size_t)EE*HH];
__device__ unsigned g_aggenc[NN*HH];
__device__ float g_agg[NN*HH];
__device__ float g_t1[NN*HH];
__device__ float g_h1[NN*HH];
__device__ float g_qkv[NN*3*HH];
__device__ float g_o[NN*HH];
__device__ float g_t2[NN*HH];
__device__ float g_h2[NN*HH];
__device__ float g_out[NN*HH];
__device__ float g_mlp1[NN*2*HH];
__device__ float g_out2[NN*HH];
__device__ float g_part[256*256];
__device__ float g_stats[256];

// ---------------- helpers ----------------------------------------------------
__device__ __forceinline__ float leaky_f(float v) { return v > 0.0f ? v : 0.01f*v; }

__device__ __forceinline__ float fast_exp(float x) {
    x = fmaxf(x, -87.0f);
    float t  = x * 1.4426950408889634f;
    float fl = floorf(t);
    float f  = t - fl;
    float p  =            1.339077600e-4f;
    p = p * f + 9.618437357e-4f;
    p = p * f + 9.556031144e-3f;
    p = p * f + 5.550332471e-2f;
    p = p * f + 2.402264923e-1f;
    p = p * f + 6.931471825e-1f;
    p = p * f + 1.0f;
    int ei = (int)fl;
    return __int_as_float((ei + 127) << 23) * p;
}

__device__ __forceinline__ unsigned enc_f(float f) {
    unsigned u = __float_as_uint(f);
    return (u & 0x80000000u) ? ~u : (u | 0x80000000u);
}
__device__ __forceinline__ float dec_f(unsigned u) {
    return (u & 0x80000000u) ? __uint_as_float(u ^ 0x80000000u) : __uint_as_float(~u);
}
#define ENC_NEGINF 0x007FFFFFu

__device__ __forceinline__ uint32_t smem_u32(const void* p) {
    uint32_t a;
    asm("{ .reg .u64 t; cvta.to.shared.u64 t, %1; cvt.u32.u64 %0, t; }" : "=r"(a) : "l"(p));
    return a;
}

// ---------------- warp-level bf16 MMA building blocks -------------------------
#define LDM_X4(r, a) \
    asm volatile("ldmatrix.sync.aligned.m8n8.x4.shared.b16 {%0,%1,%2,%3}, [%4];" \
        : "=r"((r)[0]), "=r"((r)[1]), "=r"((r)[2]), "=r"((r)[3]) : "r"(a))
#define LDM_X4T(r, a) \
    asm volatile("ldmatrix.sync.aligned.m8n8.x4.trans.shared.b16 {%0,%1,%2,%3}, [%4];" \
        : "=r"((r)[0]), "=r"((r)[1]), "=r"((r)[2]), "=r"((r)[3]) : "r"(a))
#define MMA16816(c, a, b) \
    asm volatile("mma.sync.aligned.m16n8k16.row.col.f32.bf16.bf16.f32 " \
        "{%0,%1,%2,%3}, {%4,%5,%6,%7}, {%8,%9}, {%0,%1,%2,%3};" \
        : "+f"((c)[0]), "+f"((c)[1]), "+f"((c)[2]), "+f"((c)[3]) \
        : "r"((a)[0]), "r"((a)[1]), "r"((a)[2]), "r"((a)[3]), "r"((b)[0]), "r"((b)[1]))

__device__ __forceinline__ void split2(float v, uint16_t& hi, uint16_t& lo) {
    __nv_bfloat16 h = __float2bfloat16(v);
    float r = v - __bfloat162float(h);
    __nv_bfloat16 l = __float2bfloat16(r);
    hi = *reinterpret_cast<uint16_t*>(&h);
    lo = *reinterpret_cast<uint16_t*>(&l);
}

// smem layout: padded stride 136 bf16 = 272 bytes per row (17x16B -> conflict-free ldmatrix)
#define SROW 272
#define TILE_B (128*SROW)       // 34816
#define SM_A_HI 0
#define SM_A_LO TILE_B
#define SM_B_HI (2*TILE_B)
#define SM_B_LO (3*TILE_B)
#define SM_TOTAL (4*TILE_B)     // 139264

// ---------------- split-bf16 3-pass GEMM on mma.sync --------------------------
// C[M,N] = epi( (PRE_LEAKY? leaky(A):A)[M,K] @ B[K,N] ),  fp32 accuracy ~1e-5
template<bool PRE_LEAKY, bool BIAS, bool ACCUMC, bool RESID, bool RELU>
__global__ void __launch_bounds__(256) mma_gemm(
    const float* __restrict__ A, const float* __restrict__ B,
    float* __restrict__ C, const float* __restrict__ bias,
    const float* __restrict__ resid, int M, int N, int K)
{
    extern __shared__ char smem[];
    uint32_t sb = smem_u32(smem);
    int tid = threadIdx.x;
    int lane = tid & 31, w = tid >> 5;
    int wm = w >> 2, wn = w & 3;             // 2 x 4 warp grid; warp tile 64(M) x 32(N)
    int mrow0 = blockIdx.y << 7, ncol0 = blockIdx.x << 7;

    float acc[4][4][4];
    #pragma unroll
    for (int i = 0; i < 4; i++)
        #pragma unroll
        for (int j = 0; j < 4; j++)
            #pragma unroll
            for (int q = 0; q < 4; q++) acc[i][j][q] = 0.0f;

    for (int kc = 0; kc < K; kc += 128) {
        __syncthreads();
        // ---- fill A (128 rows x 128 k), split fp32 -> bf16 hi/lo ----
        for (int idx = tid * 4; idx < 128 * 128; idx += 1024) {
            int m = idx >> 7, c = idx & 127;
            float4 v = make_float4(0.f, 0.f, 0.f, 0.f);
            if (mrow0 + m < M)
                v = *reinterpret_cast<const float4*>(A + (size_t)(mrow0 + m) * K + kc + c);
            if (PRE_LEAKY) { v.x = leaky_f(v.x); v.y = leaky_f(v.y); v.z = leaky_f(v.z); v.w = leaky_f(v.w); }
            uint16_t h0,l0,h1,l1,h2,l2,h3,l3;
            split2(v.x,h0,l0); split2(v.y,h1,l1); split2(v.z,h2,l2); split2(v.w,h3,l3);
            uint32_t o = (uint32_t)(m * SROW + c * 2);
            *reinterpret_cast<uint2*>(smem + SM_A_HI + o) =
                make_uint2((uint32_t)h0 | ((uint32_t)h1<<16), (uint32_t)h2 | ((uint32_t)h3<<16));
            *reinterpret_cast<uint2*>(smem + SM_A_LO + o) =
                make_uint2((uint32_t)l0 | ((uint32_t)l1<<16), (uint32_t)l2 | ((uint32_t)l3<<16));
        }
        // ---- fill B (128 k x 128 n), row-major [k][n] ----
        for (int idx = tid * 4; idx < 128 * 128; idx += 1024) {
            int kk2 = idx >> 7, c = idx & 127;
            float4 v = *reinterpret_cast<const float4*>(B + (size_t)(kc + kk2) * N + ncol0 + c);
            uint16_t h0,l0,h1,l1,h2,l2,h3,l3;
            split2(v.x,h0,l0); split2(v.y,h1,l1); split2(v.z,h2,l2); split2(v.w,h3,l3);
            uint32_t o = (uint32_t)(kk2 * SROW + c * 2);
            *reinterpret_cast<uint2*>(smem + SM_B_HI + o) =
                make_uint2((uint32_t)h0 | ((uint32_t)h1<<16), (uint32_t)h2 | ((uint32_t)h3<<16));
            *reinterpret_cast<uint2*>(smem + SM_B_LO + o) =
                make_uint2((uint32_t)l0 | ((uint32_t)l1<<16), (uint32_t)l2 | ((uint32_t)l3<<16));
        }
        __syncthreads();

        #pragma unroll
        for (int kk = 0; kk < 8; kk++) {
            int k0 = kk << 4;
            uint32_t ah[4][4], al[4][4];
            #pragma unroll
            for (int i = 0; i < 4; i++) {
                uint32_t ra = sb + SM_A_HI +
                    (uint32_t)((wm*64 + i*16 + (lane & 15)) * SROW + (k0 + ((lane >> 4) << 3)) * 2);
                LDM_X4(ah[i], ra);
                LDM_X4(al[i], ra + (SM_A_LO - SM_A_HI));
            }
            uint32_t bh[4][2], bl[4][2];
            #pragma unroll
            for (int jj = 0; jj < 2; jj++) {
                uint32_t rb = sb + SM_B_HI +
                    (uint32_t)((k0 + (lane & 15)) * SROW + (wn*32 + jj*16 + ((lane >> 4) << 3)) * 2);
                uint32_t t[4];
                LDM_X4T(t, rb);
                bh[jj*2][0] = t[0]; bh[jj*2][1] = t[1];
                bh[jj*2+1][0] = t[2]; bh[jj*2+1][1] = t[3];
                LDM_X4T(t, rb + (SM_B_LO - SM_B_HI));
                bl[jj*2][0] = t[0]; bl[jj*2][1] = t[1];
                bl[jj*2+1][0] = t[2]; bl[jj*2+1][1] = t[3];
            }
            #pragma unroll
            for (int i = 0; i < 4; i++)
                #pragma unroll
                for (int j = 0; j < 4; j++) {
                    MMA16816(acc[i][j], ah[i], bh[j]);
                    MMA16816(acc[i][j], ah[i], bl[j]);
                    MMA16816(acc[i][j], al[i], bh[j]);
                }
        }
    }

    // ---- epilogue ----
    #pragma unroll
    for (int i = 0; i < 4; i++) {
        int rbase = mrow0 + wm*64 + i*16 + (lane >> 2);
        #pragma unroll
        for (int half = 0; half < 2; half++) {
            int r = rbase + half*8;
            if (r < M) {
                #pragma unroll
                for (int j = 0; j < 4; j++) {
                    int c = ncol0 + wn*32 + j*8 + (lane & 3)*2;
                    size_t idx = (size_t)r * N + c;
                    float2 v = make_float2(acc[i][j][half*2], acc[i][j][half*2 + 1]);
                    if (ACCUMC) { float2 t = *reinterpret_cast<float2*>(C + idx); v.x += t.x; v.y += t.y; }
                    if (BIAS)   { v.x += bias[c]; v.y += bias[c + 1]; }
                    if (RESID)  { float2 t = *reinterpret_cast<const float2*>(resid + idx); v.x += t.x; v.y += t.y; }
                    if (RELU)   { v.x = fmaxf(v.x, 0.f); v.y = fmaxf(v.y, 0.f); }
                    *reinterpret_cast<float2*>(C + idx) = v;
                }
            }
        }
    }
}

// ---------------- small kernels ----------------------------------------------
__global__ void cvec_k(const float* __restrict__ b_ee, const float* __restrict__ M0) {
    int j = threadIdx.x;
    float s = 0.0f;
    for (int t = 0; t < HH; t++) s += b_ee[t] * M0[(size_t)(4*HH + t)*HH + j];
    g_cvec[j] = s;
}

__global__ void edge_gather_add_k(const int* __restrict__ src, const int* __restrict__ dst,
                                  const int* __restrict__ batch, int E)
{
    int idx = blockIdx.x*blockDim.x + threadIdx.x;
    int e = idx >> 5; int c4 = idx & 31;
    if (e >= E) return;
    int s = src[e], d = dst[e];
    int g = batch[d];
    float4* m0 = (float4*)g_e0;
    const float4* zD = (const float4*)g_zD;
    const float4* zS = (const float4*)g_zS;
    const float4* GD = (const float4*)g_GD;
    const float4* cv = (const float4*)g_cvec;
    float4 v = m0[(size_t)e*32 + c4];
    float4 a = zD[(size_t)d*32 + c4];
    float4 b = zS[(size_t)s*32 + c4];
    float4 c = GD[(size_t)g*32 + c4];
    float4 k = cv[c4];
    v.x += a.x + b.x + c.x + k.x;
    v.y += a.y + b.y + c.y + k.y;
    v.z += a.z + b.z + c.z + k.z;
    v.w += a.w + b.w + c.w + k.w;
    m0[(size_t)e*32 + c4] = v;
}

__global__ void agg_init_k(int total) {
    int i = blockIdx.x*blockDim.x + threadIdx.x;
    if (i < total) g_aggenc[i] = ENC_NEGINF;
}

__global__ void seg_max_k(const float* __restrict__ m3, const int* __restrict__ dst, int E) {
    int idx = blockIdx.x*blockDim.x + threadIdx.x;
    int e = idx >> 7; int c = idx & 127;
    if (e >= E) return;
    float v = m3[(size_t)e*HH + c];
    atomicMax(&g_aggenc[dst[e]*HH + c], enc_f(v));
}

__global__ void agg_decode_k(int total) {
    int i = blockIdx.x*blockDim.x + threadIdx.x;
    if (i >= total) return;
    float f = dec_f(g_aggenc[i]);
    if (!isfinite(f)) f = 0.0f;
    g_agg[i] = f;
}

__global__ void __launch_bounds__(512) attn_k(const float* __restrict__ qkv,
                                              float* __restrict__ o, int PER)
{
    __shared__ float Ks[128][32];
    __shared__ float Vs[128][32];
    int g = blockIdx.x, h = blockIdx.y;
    int tid = threadIdx.x;
    int n = g*PER + tid;
    const float scale = 0.17677669529663687f;
    float q[32];
    #pragma unroll
    for (int d = 0; d < 32; d++)
        q[d] = qkv[(size_t)n*384 + h*32 + d] * scale;

    float m = -INFINITY, l = 0.0f;
    float acc[32];
    #pragma unroll
    for (int d = 0; d < 32; d++) acc[d] = 0.0f;

    for (int c0 = 0; c0 < PER; c0 += 128) {
        __syncthreads();
        for (int i = tid; i < 128*32; i += 512) {
            int r = i >> 5, d = i & 31;
            size_t base = (size_t)(g*PER + c0 + r)*384 + h*32 + d;
            Ks[r][d] = qkv[base + 128];
            Vs[r][d] = qkv[base + 256];
        }
        __syncthreads();
        for (int j = 0; j < 128; j++) {
            float s = 0.0f;
            #pragma unroll
            for (int d = 0; d < 32; d++) s += q[d]*Ks[j][d];
            float mn = fmaxf(m, s);
            float a = fast_exp(m - mn);
            float p = fast_exp(s - mn);
            l = l*a + p;
            #pragma unroll
            for (int d = 0; d < 32; d++) acc[d] = acc[d]*a + p*Vs[j][d];
            m = mn;
        }
    }
    float inv = 1.0f / l;
    #pragma unroll
    for (int d = 0; d < 32; d++)
        o[(size_t)n*HH + h*32 + d] = acc[d]*inv;
}

__global__ void bn_stats1_k(const float* __restrict__ x, int rowsPer) {
    int c = threadIdx.x;
    int b = blockIdx.x;
    size_t r0 = (size_t)b * rowsPer;
    float s = 0.0f, s2 = 0.0f;
    for (int r = 0; r < rowsPer; r++) {
        float v = x[(r0 + r)*HH + c];
        s += v; s2 += v*v;
    }
    g_part[b*256 + c] = s;
    g_part[b*256 + 128 + c] = s2;
}
__global__ void bn_stats2_k(int nb, float invN) {
    int c = threadIdx.x;
    float s = 0.0f, s2 = 0.0f;
    for (int b = 0; b < nb; b++) { s += g_part[b*256 + c]; s2 += g_part[b*256 + 128 + c]; }
    float mu = s * invN;
    float var = s2 * invN - mu*mu;
    g_stats[c] = mu;
    g_stats[128 + c] = rsqrtf(var + 1e-5f);
}
__global__ void bn_apply_k(const float* __restrict__ x, const float* __restrict__ w,
                           const float* __restrict__ b, float* __restrict__ y, int total)
{
    int i = blockIdx.x*blockDim.x + threadIdx.x;
    if (i >= total) return;
    int c = i & 127;
    y[i] = (x[i] - g_stats[c]) * g_stats[128 + c] * w[c] + b[c];
}

__global__ void add_k(const float* __restrict__ a, const float* __restrict__ b,
                      float* __restrict__ y, int total)
{
    int i = blockIdx.x*blockDim.x + threadIdx.x;
    if (i < total) y[i] = a[i] + b[i];
}

// ---------------- host orchestration -----------------------------------------
template<bool PL, bool BI, bool AC, bool RE, bool RL>
static inline void run_mma(const float* A, const float* B, float* C,
                           const float* bias, const float* resid, int M, int N, int K)
{
    cudaFuncSetAttribute(mma_gemm<PL,BI,AC,RE,RL>,
                         cudaFuncAttributeMaxDynamicSharedMemorySize, SM_TOTAL);
    dim3 grid(N / 128, (M + 127) / 128);
    mma_gemm<PL,BI,AC,RE,RL><<<grid, 256, SM_TOTAL>>>(A, B, C, bias, resid, M, N, K);
}

extern "C" void kernel_launch(void* const* d_in, const int* in_sizes, int n_in,
                              void* d_out, int out_size)
{
    const float* node_fts  = (const float*)d_in[0];
    const float* edge_attr = (const float*)d_in[1];
    const float* graph_fts = (const float*)d_in[2];
    const float* hidden    = (const float*)d_in[3];
    const float* W_ee      = (const float*)d_in[4];
    const float* b_ee      = (const float*)d_in[5];
    const float* M0        = (const float*)d_in[6];
    const float* M1        = (const float*)d_in[7];
    const float* M2        = (const float*)d_in[8];
    const float* M3        = (const float*)d_in[9];
    const float* U1        = (const float*)d_in[10];
    const float* U2        = (const float*)d_in[11];
    const float* Wqkv      = (const float*)d_in[12];
    const float* bqkv      = (const float*)d_in[13];
    const float* Wo        = (const float*)d_in[14];
    const float* bo        = (const float*)d_in[15];
    const float* bn1_w     = (const float*)d_in[16];
    const float* bn1_b     = (const float*)d_in[17];
    const float* bn2_w     = (const float*)d_in[18];
    const float* bn2_b     = (const float*)d_in[19];
    const float* bn3_w     = (const float*)d_in[20];
    const float* bn3_b     = (const float*)d_in[21];
    const float* W1        = (const float*)d_in[22];
    const float* b1        = (const float*)d_in[23];
    const float* W2        = (const float*)d_in[24];
    const float* b2        = (const float*)d_in[25];
    const int*   edge_index= (const int*)d_in[26];
    const int*   batch     = (const int*)d_in[27];

    const int N = in_sizes[0] / HH;
    const int E = in_sizes[1] / HH;
    const int G = in_sizes[2] / HH;
    const int PER = N / G;
    const int* src = edge_index;
    const int* dst = edge_index + E;
    float* outp = (float*)d_out;

    float *pC, *pGD, *pzD, *pzS, *pe0, *pe1, *pagg, *pt1, *ph1, *pqkv, *po, *pt2, *ph2, *pout, *pmlp1, *pout2;
    cudaGetSymbolAddress((void**)&pC,    g_C);
    cudaGetSymbolAddress((void**)&pGD,   g_GD);
    cudaGetSymbolAddress((void**)&pzD,   g_zD);
    cudaGetSymbolAddress((void**)&pzS,   g_zS);
    cudaGetSymbolAddress((void**)&pe0,   g_e0);
    cudaGetSymbolAddress((void**)&pe1,   g_e1);
    cudaGetSymbolAddress((void**)&pagg,  g_agg);
    cudaGetSymbolAddress((void**)&pt1,   g_t1);
    cudaGetSymbolAddress((void**)&ph1,   g_h1);
    cudaGetSymbolAddress((void**)&pqkv,  g_qkv);
    cudaGetSymbolAddress((void**)&po,    g_o);
    cudaGetSymbolAddress((void**)&pt2,   g_t2);
    cudaGetSymbolAddress((void**)&ph2,   g_h2);
    cudaGetSymbolAddress((void**)&pout,  g_out);
    cudaGetSymbolAddress((void**)&pmlp1, g_mlp1);
    cudaGetSymbolAddress((void**)&pout2, g_out2);

    // ---- tiny precomputes -------------------------------------------------
    run_mma<false,false,false,false,false>(W_ee, M0 + (size_t)4*HH*HH, pC, nullptr, nullptr, HH, HH, HH);
    cvec_k<<<1, HH>>>(b_ee, M0);
    run_mma<false,false,false,false,false>(graph_fts, M0 + (size_t)5*HH*HH, pGD, nullptr, nullptr, G, HH, HH);

    // ---- node-side M0 folds ----------------------------------------------
    run_mma<false,false,false,false,false>(node_fts, M0,                   pzD, nullptr, nullptr, N, HH, HH);
    run_mma<false,false,true ,false,false>(hidden,   M0 + (size_t)1*HH*HH, pzD, nullptr, nullptr, N, HH, HH);
    run_mma<false,false,false,false,false>(node_fts, M0 + (size_t)2*HH*HH, pzS, nullptr, nullptr, N, HH, HH);
    run_mma<false,false,true ,false,false>(hidden,   M0 + (size_t)3*HH*HH, pzS, nullptr, nullptr, N, HH, HH);

    // ---- edge pipeline ----------------------------------------------------
    run_mma<false,false,false,false,false>(edge_attr, pC, pe0, nullptr, nullptr, E, HH, HH);
    {
        int total = E*32;
        edge_gather_add_k<<<(total + 255)/256, 256>>>(src, dst, batch, E);
    }
    run_mma<true,false,false,false,false>(pe0, M1, pe1, nullptr, nullptr, E, HH, HH);
    run_mma<true,false,false,false,false>(pe1, M2, pe0, nullptr, nullptr, E, HH, HH);
    run_mma<true,false,false,false,false>(pe0, M3, pe1, nullptr, nullptr, E, HH, HH);

    // ---- segment max ------------------------------------------------------
    {
        int total = N*HH;
        agg_init_k<<<(total + 255)/256, 256>>>(total);
        int et = E*HH;
        seg_max_k<<<(et + 255)/256, 256>>>(pe1, dst, E);
        agg_decode_k<<<(total + 255)/256, 256>>>(total);
    }

    // ---- h1 = BN1(h_local + node_fts) ------------------------------------
    run_mma<false,false,false,false,false>(node_fts, U1,                 pt1, nullptr, nullptr, N, HH, HH);
    run_mma<false,false,true ,false,false>(hidden,   U1 + (size_t)HH*HH, pt1, nullptr, nullptr, N, HH, HH);
    run_mma<false,false,true ,true ,false>(pagg, U2, pt1, nullptr, node_fts, N, HH, HH);
    {
        int rowsPer = N/256;
        bn_stats1_k<<<256, 128>>>(pt1, rowsPer);
        bn_stats2_k<<<1, 128>>>(256, 1.0f/(float)N);
        int total = N*HH;
        bn_apply_k<<<(total + 255)/256, 256>>>(pt1, bn1_w, bn1_b, ph1, total);
    }

    // ---- attention --------------------------------------------------------
    run_mma<false,true,false,false,false>(node_fts, Wqkv, pqkv, bqkv, nullptr, N, 3*HH, HH);
    attn_k<<<dim3(G, 4), PER>>>(pqkv, po, PER);
    run_mma<false,true,false,true,false>(po, Wo, pt2, bo, node_fts, N, HH, HH);
    {
        int rowsPer = N/256;
        bn_stats1_k<<<256, 128>>>(pt2, rowsPer);
        bn_stats2_k<<<1, 128>>>(256, 1.0f/(float)N);
        int total = N*HH;
        bn_apply_k<<<(total + 255)/256, 256>>>(pt2, bn2_w, bn2_b, ph2, total);
    }

    // ---- combine + MLP ----------------------------------------------------
    {
        int total = N*HH;
        add_k<<<(total + 255)/256, 256>>>(ph1, ph2, pout, total);
    }
    run_mma<false,true,false,false,true>(pout, W1, pmlp1, b1, nullptr, N, 2*HH, HH);
    run_mma<false,true,false,true,false>(pmlp1, W2, pout2, b2, pout, N, HH, 2*HH);

    // ---- BN3 -> output ----------------------------------------------------
    {
        int rowsPer = N/256;
        bn_stats1_k<<<256, 128>>>(pout2, rowsPer);
        bn_stats2_k<<<1, 128>>>(256, 1.0f/(float)N);
        int total = N*HH;
        bn_apply_k<<<(total + 255)/256, 256>>>(pout2, bn3_w, bn3_b, outp, total);
    }
}

// round 7
// speedup vs baseline: 1.7938x; 1.4347x over previous
#include <cuda_runtime.h>
#include <cuda_bf16.h>
#include <math.h>
#include <stdint.h>

typedef unsigned short u16;

// Problem constants
#define NN 32768
#define EE 262144
#define GG 64
#define HH 128

// ---------------- scratch ----------------------------------------------------
// split weights (hi/lo bf16)
__device__ u16 g_wM0z_h[4*HH*HH], g_wM0z_l[4*HH*HH];
__device__ u16 g_wM0c_h[HH*HH],   g_wM0c_l[HH*HH];
__device__ u16 g_wM0d_h[HH*HH],   g_wM0d_l[HH*HH];
__device__ u16 g_wee_h[HH*HH],    g_wee_l[HH*HH];
__device__ u16 g_wM1_h[HH*HH],    g_wM1_l[HH*HH];
__device__ u16 g_wM2_h[HH*HH],    g_wM2_l[HH*HH];
__device__ u16 g_wM3_h[HH*HH],    g_wM3_l[HH*HH];
__device__ u16 g_wU1_h[2*HH*HH],  g_wU1_l[2*HH*HH];
__device__ u16 g_wU2_h[HH*HH],    g_wU2_l[HH*HH];
__device__ u16 g_wQKV_h[3*HH*HH], g_wQKV_l[3*HH*HH];
__device__ u16 g_wWo_h[HH*HH],    g_wWo_l[HH*HH];
__device__ u16 g_wW1_h[2*HH*HH],  g_wW1_l[2*HH*HH];
__device__ u16 g_wW2_h[2*HH*HH],  g_wW2_l[2*HH*HH];
__device__ u16 g_wC_h[HH*HH],     g_wC_l[HH*HH];      // C = W_ee@M0c split
__device__ u16 g_wG_h[GG*HH],     g_wG_l[GG*HH];      // graph_fts split
// activations
__device__ float g_cvec[HH];
__device__ float g_GD[GG*HH];
__device__ float g_zD[NN*HH];
__device__ float g_zS[NN*HH];
__device__ u16 g_z_h[NN*2*HH], g_z_l[NN*2*HH];
__device__ u16 g_m0h[(size_t)EE*HH], g_m0l[(size_t)EE*HH];
__device__ u16 g_m1h[(size_t)EE*HH], g_m1l[(size_t)EE*HH];
__device__ unsigned g_aggenc[NN*HH];
__device__ u16 g_agh[NN*HH], g_agl[NN*HH];
__device__ float g_t1[NN*HH];
__device__ float g_h1[NN*HH];
__device__ float g_qkv[NN*3*HH];
__device__ u16 g_oh[NN*HH], g_ol[NN*HH];
__device__ float g_t2[NN*HH];
__device__ float g_h2[NN*HH];
__device__ float g_out[NN*HH];
__device__ u16 g_outh[NN*HH], g_outl[NN*HH];
__device__ u16 g_mlp1h[NN*2*HH], g_mlp1l[NN*2*HH];
__device__ float g_out2[NN*HH];
__device__ float g_part[256*256];
__device__ float g_stats[256];

// ---------------- helpers ----------------------------------------------------
__device__ __forceinline__ float leaky_f(float v) { return v > 0.0f ? v : 0.01f*v; }

__device__ __forceinline__ float fast_exp(float x) {
    x = fmaxf(x, -87.0f);
    float t  = x * 1.4426950408889634f;
    float fl = floorf(t);
    float f  = t - fl;
    float p  =            1.339077600e-4f;
    p = p * f + 9.618437357e-4f;
    p = p * f + 9.556031144e-3f;
    p = p * f + 5.550332471e-2f;
    p = p * f + 2.402264923e-1f;
    p = p * f + 6.931471825e-1f;
    p = p * f + 1.0f;
    int ei = (int)fl;
    return __int_as_float((ei + 127) << 23) * p;
}

__device__ __forceinline__ unsigned enc_f(float f) {
    unsigned u = __float_as_uint(f);
    return (u & 0x80000000u) ? ~u : (u | 0x80000000u);
}
__device__ __forceinline__ float dec_f(unsigned u) {
    return (u & 0x80000000u) ? __uint_as_float(u ^ 0x80000000u) : __uint_as_float(~u);
}
#define ENC_NEGINF 0x007FFFFFu

__device__ __forceinline__ uint32_t smem_u32(const void* p) {
    uint32_t a;
    asm("{ .reg .u64 t; cvta.to.shared.u64 t, %1; cvt.u32.u64 %0, t; }" : "=r"(a) : "l"(p));
    return a;
}

__device__ __forceinline__ void split2(float v, u16& hi, u16& lo) {
    __nv_bfloat16 h = __float2bfloat16(v);
    float r = v - __bfloat162float(h);
    __nv_bfloat16 l = __float2bfloat16(r);
    hi = *reinterpret_cast<u16*>(&h);
    lo = *reinterpret_cast<u16*>(&l);
}
__device__ __forceinline__ u16 hi_of(float v) {
    __nv_bfloat16 h = __float2bfloat16(v);
    return *reinterpret_cast<u16*>(&h);
}

// ---------------- MMA building blocks ----------------------------------------
#define LDM_X4(r, a) \
    asm volatile("ldmatrix.sync.aligned.m8n8.x4.shared.b16 {%0,%1,%2,%3}, [%4];" \
        : "=r"((r)[0]), "=r"((r)[1]), "=r"((r)[2]), "=r"((r)[3]) : "r"(a))
#define LDM_X4T(r, a) \
    asm volatile("ldmatrix.sync.aligned.m8n8.x4.trans.shared.b16 {%0,%1,%2,%3}, [%4];" \
        : "=r"((r)[0]), "=r"((r)[1]), "=r"((r)[2]), "=r"((r)[3]) : "r"(a))
#define MMA16816(c, a, b) \
    asm volatile("mma.sync.aligned.m16n8k16.row.col.f32.bf16.bf16.f32 " \
        "{%0,%1,%2,%3}, {%4,%5,%6,%7}, {%8,%9}, {%0,%1,%2,%3};" \
        : "+f"((c)[0]), "+f"((c)[1]), "+f"((c)[2]), "+f"((c)[3]) \
        : "r"((a)[0]), "r"((a)[1]), "r"((a)[2]), "r"((a)[3]), "r"((b)[0]), "r"((b)[1]))

#define CPA16(dst, src) asm volatile("cp.async.cg.shared.global [%0], [%1], 16;" :: "r"(dst), "l"(src))
#define CPA_COMMIT()    asm volatile("cp.async.commit_group;")
#define CPA_WAIT0()     asm volatile("cp.async.wait_group 0;" ::: "memory")

// XOR-swizzled offset inside a tile: rows of 256B, 16B chunks 0..15
__device__ __forceinline__ uint32_t swz(int row, int cb) {
    return (uint32_t)((row << 8) + (((cb ^ row) & 7) << 4) + ((cb & 8) << 4));
}

// ---------------- split-bf16 3-pass GEMM on mma.sync --------------------------
// Tile 64(M) x 128(N); 8 warps = 2x4; warp tile 32x32.
// A, B presplit bf16 hi/lo (row-major, lda/ldb in elements), except AF32.
// OUT: 0 = fp32 Cf (BIAS/ACCUM/RESID/ACT flags)
//      1 = split out to Ch/Cl (BIAS + ACT applied first)
//      2 = atomicMax(enc) into aggenc rows dst[r]
//      3 = gather-epilogue: v += zD[dst]+zS[src]+GD[g]+cvec; leaky; split to Ch/Cl
template<int OUT, int ACT, bool BIAS, bool ACCUM, bool RESID, bool AF32>
__global__ void __launch_bounds__(256,2) gemm_ps(
    const void* Ah_, const u16* Al, int lda,
    const u16* __restrict__ Bh, const u16* __restrict__ Bl, int ldb,
    float* Cf, u16* Ch, u16* Cl,
    const float* __restrict__ bias, const float* __restrict__ resid,
    const int* __restrict__ srcv, const int* __restrict__ dstv,
    const float* __restrict__ zD, const float* __restrict__ zS,
    const float* __restrict__ GD, const float* __restrict__ cvec,
    unsigned* aggenc, int M, int N, int K, int PER)
{
    extern __shared__ char smem[];
    uint32_t sb = smem_u32(smem);
    const int tid = threadIdx.x;
    const int lane = tid & 31, w = tid >> 5;
    const int wm = w >> 2, wn = w & 3;
    const int mrow0 = blockIdx.y << 6, ncol0 = blockIdx.x << 7;

    const uint32_t offB_h = 0;
    const uint32_t offB_l = (uint32_t)K * 256;
    const uint32_t offA_h = (uint32_t)K * 512;
    const uint32_t offA_l = offA_h + 16384;

    // ---- B fill (whole K), cp.async ----
    for (int idx = tid; idx < K * 16; idx += 256) {
        int row = idx >> 4, cb = idx & 15;
        size_t so = (size_t)row * ldb + ncol0 + cb * 8;
        uint32_t d = swz(row, cb);
        CPA16(sb + offB_h + d, Bh + so);
        CPA16(sb + offB_l + d, Bl + so);
    }

    float acc[2][4][4];
    #pragma unroll
    for (int i = 0; i < 2; i++)
        #pragma unroll
        for (int j = 0; j < 4; j++)
            #pragma unroll
            for (int q = 0; q < 4; q++) acc[i][j][q] = 0.0f;

    for (int kc = 0; kc < K; kc += 128) {
        // ---- A chunk fill ----
        if (AF32) {
            const float* Af = (const float*)Ah_;
            for (int idx = tid; idx < 64 * 16; idx += 256) {
                int row = idx >> 4, cb = idx & 15;
                const float* ap = Af + (size_t)(mrow0 + row) * lda + kc + cb * 8;
                float4 v0 = *reinterpret_cast<const float4*>(ap);
                float4 v1 = *reinterpret_cast<const float4*>(ap + 4);
                u16 h[8], l[8];
                split2(v0.x,h[0],l[0]); split2(v0.y,h[1],l[1]);
                split2(v0.z,h[2],l[2]); split2(v0.w,h[3],l[3]);
                split2(v1.x,h[4],l[4]); split2(v1.y,h[5],l[5]);
                split2(v1.z,h[6],l[6]); split2(v1.w,h[7],l[7]);
                uint32_t d = swz(row, cb);
                *reinterpret_cast<uint4*>(smem + offA_h + d) = make_uint4(
                    (uint32_t)h[0]|((uint32_t)h[1]<<16), (uint32_t)h[2]|((uint32_t)h[3]<<16),
                    (uint32_t)h[4]|((uint32_t)h[5]<<16), (uint32_t)h[6]|((uint32_t)h[7]<<16));
                *reinterpret_cast<uint4*>(smem + offA_l + d) = make_uint4(
                    (uint32_t)l[0]|((uint32_t)l[1]<<16), (uint32_t)l[2]|((uint32_t)l[3]<<16),
                    (uint32_t)l[4]|((uint32_t)l[5]<<16), (uint32_t)l[6]|((uint32_t)l[7]<<16));
            }
        } else {
            const u16* Ah = (const u16*)Ah_;
            for (int idx = tid; idx < 64 * 16; idx += 256) {
                int row = idx >> 4, cb = idx & 15;
                size_t so = (size_t)(mrow0 + row) * lda + kc + cb * 8;
                uint32_t d = swz(row, cb);
                CPA16(sb + offA_h + d, Ah + so);
                CPA16(sb + offA_l + d, Al + so);
            }
        }
        CPA_COMMIT();
        CPA_WAIT0();
        __syncthreads();

        // ---- compute 8 k-steps ----
        #pragma unroll
        for (int kk = 0; kk < 8; kk++) {
            uint32_t ah[2][4], al[2][4];
            #pragma unroll
            for (int i = 0; i < 2; i++) {
                int row = wm*32 + i*16 + (lane & 15);
                uint32_t ad = sb + offA_h + swz(row, kk*2 + (lane >> 4));
                LDM_X4(ah[i], ad);
                LDM_X4(al[i], ad + 16384);
            }
            uint32_t bh[4][2], bl[4][2];
            #pragma unroll
            for (int jj = 0; jj < 2; jj++) {
                int krow = kc + kk*16 + (lane & 15);
                uint32_t bd = sb + offB_h + swz(krow, wn*4 + jj*2 + (lane >> 4));
                uint32_t t[4];
                LDM_X4T(t, bd);
                bh[jj*2][0]=t[0]; bh[jj*2][1]=t[1]; bh[jj*2+1][0]=t[2]; bh[jj*2+1][1]=t[3];
                LDM_X4T(t, bd + offB_l);
                bl[jj*2][0]=t[0]; bl[jj*2][1]=t[1]; bl[jj*2+1][0]=t[2]; bl[jj*2+1][1]=t[3];
            }
            #pragma unroll
            for (int i = 0; i < 2; i++)
                #pragma unroll
                for (int j = 0; j < 4; j++) {
                    MMA16816(acc[i][j], ah[i], bh[j]);
                    MMA16816(acc[i][j], ah[i], bl[j]);
                    MMA16816(acc[i][j], al[i], bh[j]);
                }
        }
        __syncthreads();
    }

    // ---- epilogue ----
    #pragma unroll
    for (int i = 0; i < 2; i++) {
        int r0 = mrow0 + wm*32 + i*16 + (lane >> 2);
        #pragma unroll
        for (int half = 0; half < 2; half++) {
            int r = r0 + half*8;
            int sidx = 0, didx = 0, gidx = 0;
            if (OUT == 2 || OUT == 3) didx = dstv[r];
            if (OUT == 3) { sidx = srcv[r]; gidx = didx / PER; }
            #pragma unroll
            for (int j = 0; j < 4; j++) {
                int c = ncol0 + wn*32 + j*8 + (lane & 3)*2;
                size_t idx = (size_t)r * N + c;
                float vx = acc[i][j][half*2], vy = acc[i][j][half*2 + 1];
                if (BIAS)  { vx += bias[c]; vy += bias[c + 1]; }
                if (OUT == 3) {
                    vx += zD[(size_t)didx*HH + c] + zS[(size_t)sidx*HH + c]
                        + GD[(size_t)gidx*HH + c] + cvec[c];
                    vy += zD[(size_t)didx*HH + c+1] + zS[(size_t)sidx*HH + c+1]
                        + GD[(size_t)gidx*HH + c+1] + cvec[c+1];
                    vx = leaky_f(vx); vy = leaky_f(vy);
                    u16 hx,lx,hy,ly; split2(vx,hx,lx); split2(vy,hy,ly);
                    *reinterpret_cast<uint32_t*>(Ch + idx) = (uint32_t)hx | ((uint32_t)hy<<16);
                    *reinterpret_cast<uint32_t*>(Cl + idx) = (uint32_t)lx | ((uint32_t)ly<<16);
                } else if (OUT == 2) {
                    atomicMax(&aggenc[didx*HH + c],   enc_f(vx));
                    atomicMax(&aggenc[didx*HH + c+1], enc_f(vy));
                } else {
                    if (ACCUM) { float2 t = *reinterpret_cast<float2*>(Cf + idx); vx += t.x; vy += t.y; }
                    if (RESID) { float2 t = *reinterpret_cast<const float2*>(resid + idx); vx += t.x; vy += t.y; }
                    if (ACT == 1) { vx = fmaxf(vx, 0.f); vy = fmaxf(vy, 0.f); }
                    else if (ACT == 2) { vx = leaky_f(vx); vy = leaky_f(vy); }
                    if (OUT == 1) {
                        u16 hx,lx,hy,ly; split2(vx,hx,lx); split2(vy,hy,ly);
                        *reinterpret_cast<uint32_t*>(Ch + idx) = (uint32_t)hx | ((uint32_t)hy<<16);
                        *reinterpret_cast<uint32_t*>(Cl + idx) = (uint32_t)lx | ((uint32_t)ly<<16);
                    } else {
                        *reinterpret_cast<float2*>(Cf + idx) = make_float2(vx, vy);
                    }
                }
            }
        }
    }
}

// ---------------- small kernels ----------------------------------------------
__global__ void split_arr_k(const float* __restrict__ src, u16* __restrict__ hi,
                            u16* __restrict__ lo, int n)
{
    int i = blockIdx.x*blockDim.x + threadIdx.x;
    if (i >= n) return;
    u16 h, l; split2(src[i], h, l);
    hi[i] = h; lo[i] = l;
}

__global__ void split_z_k(const float* __restrict__ node, const float* __restrict__ hid, int n)
{
    int i = blockIdx.x*blockDim.x + threadIdx.x;
    if (i >= n) return;
    int row = i >> 8, col = i & 255;
    float v = (col < 128) ? node[row*HH + col] : hid[row*HH + col - 128];
    u16 h, l; split2(v, h, l);
    g_z_h[i] = h; g_z_l[i] = l;
}

__global__ void cvec_k(const float* __restrict__ b_ee, const float* __restrict__ M0) {
    int j = threadIdx.x;
    float s = 0.0f;
    for (int t = 0; t < HH; t++) s += b_ee[t] * M0[(size_t)(4*HH + t)*HH + j];
    g_cvec[j] = s;
}

__global__ void agg_init_k(int total) {
    int i = blockIdx.x*blockDim.x + threadIdx.x;
    if (i < total) g_aggenc[i] = ENC_NEGINF;
}

__global__ void agg_decode_k(int total) {
    int i = blockIdx.x*blockDim.x + threadIdx.x;
    if (i >= total) return;
    float f = dec_f(g_aggenc[i]);
    if (!isfinite(f)) f = 0.0f;
    u16 h, l; split2(f, h, l);
    g_agh[i] = h; g_agl[i] = l;
}

__global__ void __launch_bounds__(512) attn_k(const float* __restrict__ qkv, int PER)
{
    __shared__ float Ks[128][32];
    __shared__ float Vs[128][32];
    int g = blockIdx.x, h = blockIdx.y;
    int tid = threadIdx.x;
    int n = g*PER + tid;
    const float scale = 0.17677669529663687f;
    float q[32];
    #pragma unroll
    for (int d = 0; d < 32; d++)
        q[d] = qkv[(size_t)n*384 + h*32 + d] * scale;

    float m = -INFINITY, l = 0.0f;
    float acc[32];
    #pragma unroll
    for (int d = 0; d < 32; d++) acc[d] = 0.0f;

    for (int c0 = 0; c0 < PER; c0 += 128) {
        __syncthreads();
        for (int i = tid; i < 128*32; i += 512) {
            int r = i >> 5, d = i & 31;
            size_t base = (size_t)(g*PER + c0 + r)*384 + h*32 + d;
            Ks[r][d] = qkv[base + 128];
            Vs[r][d] = qkv[base + 256];
        }
        __syncthreads();
        for (int j = 0; j < 128; j++) {
            float s = 0.0f;
            #pragma unroll
            for (int d = 0; d < 32; d++) s += q[d]*Ks[j][d];
            float mn = fmaxf(m, s);
            float a = fast_exp(m - mn);
            float p = fast_exp(s - mn);
            l = l*a + p;
            #pragma unroll
            for (int d = 0; d < 32; d++) acc[d] = acc[d]*a + p*Vs[j][d];
            m = mn;
        }
    }
    float inv = 1.0f / l;
    #pragma unroll
    for (int d = 0; d < 32; d += 2) {
        float vx = acc[d]*inv, vy = acc[d+1]*inv;
        u16 hx,lx,hy,ly; split2(vx,hx,lx); split2(vy,hy,ly);
        size_t idx = (size_t)n*HH + h*32 + d;
        *reinterpret_cast<uint32_t*>(g_oh + idx) = (uint32_t)hx | ((uint32_t)hy<<16);
        *reinterpret_cast<uint32_t*>(g_ol + idx) = (uint32_t)lx | ((uint32_t)ly<<16);
    }
}

__global__ void bn_stats1_k(const float* __restrict__ x, int rowsPer) {
    int c = threadIdx.x;
    int b = blockIdx.x;
    size_t r0 = (size_t)b * rowsPer;
    float s = 0.0f, s2 = 0.0f;
    for (int r = 0; r < rowsPer; r++) {
        float v = x[(r0 + r)*HH + c];
        s += v; s2 += v*v;
    }
    g_part[b*256 + c] = s;
    g_part[b*256 + 128 + c] = s2;
}
__global__ void bn_stats2_k(int nb, float invN) {
    int c = threadIdx.x;
    float s = 0.0f, s2 = 0.0f;
    for (int b = 0; b < nb; b++) { s += g_part[b*256 + c]; s2 += g_part[b*256 + 128 + c]; }
    float mu = s * invN;
    float var = s2 * invN - mu*mu;
    g_stats[c] = mu;
    g_stats[128 + c] = rsqrtf(var + 1e-5f);
}
__global__ void bn_apply_k(const float* __restrict__ x, const float* __restrict__ w,
                           const float* __restrict__ b, float* __restrict__ y, int total)
{
    int i = blockIdx.x*blockDim.x + threadIdx.x;
    if (i >= total) return;
    int c = i & 127;
    y[i] = (x[i] - g_stats[c]) * g_stats[128 + c] * w[c] + b[c];
}

__global__ void add_split_k(const float* __restrict__ a, const float* __restrict__ b, int total)
{
    int i = blockIdx.x*blockDim.x + threadIdx.x;
    if (i >= total) return;
    float v = a[i] + b[i];
    g_out[i] = v;
    u16 h, l; split2(v, h, l);
    g_outh[i] = h; g_outl[i] = l;
}

// ---------------- host orchestration -----------------------------------------
template<int OUT, int ACT, bool BIAS, bool ACCUM, bool RESID, bool AF32>
static void run_gemm(const void* Ah, const u16* Al, int lda,
                     const u16* Bh, const u16* Bl, int ldb,
                     float* Cf, u16* Ch, u16* Cl,
                     const float* bias, const float* resid,
                     const int* srcv, const int* dstv,
                     const float* zD, const float* zS, const float* GD, const float* cvec,
                     unsigned* aggenc, int M, int N, int K, int PER)
{
    auto kfn = gemm_ps<OUT,ACT,BIAS,ACCUM,RESID,AF32>;
    cudaFuncSetAttribute(kfn, cudaFuncAttributeMaxDynamicSharedMemorySize, 163840);
    size_t smemsz = (size_t)K*512 + 32768;
    dim3 grid(N/128, M/64);
    kfn<<<grid, 256, smemsz>>>(Ah, Al, lda, Bh, Bl, ldb, Cf, Ch, Cl, bias, resid,
                               srcv, dstv, zD, zS, GD, cvec, aggenc, M, N, K, PER);
}

#define SYMADDR(p, s) cudaGetSymbolAddress((void**)&p, s)

extern "C" void kernel_launch(void* const* d_in, const int* in_sizes, int n_in,
                              void* d_out, int out_size)
{
    const float* node_fts  = (const float*)d_in[0];
    const float* edge_attr = (const float*)d_in[1];
    const float* graph_fts = (const float*)d_in[2];
    const float* hidden    = (const float*)d_in[3];
    const float* W_ee      = (const float*)d_in[4];
    const float* b_ee      = (const float*)d_in[5];
    const float* M0        = (const float*)d_in[6];
    const float* M1        = (const float*)d_in[7];
    const float* M2        = (const float*)d_in[8];
    const float* M3        = (const float*)d_in[9];
    const float* U1        = (const float*)d_in[10];
    const float* U2        = (const float*)d_in[11];
    const float* Wqkv      = (const float*)d_in[12];
    const float* bqkv      = (const float*)d_in[13];
    const float* Wo        = (const float*)d_in[14];
    const float* bo        = (const float*)d_in[15];
    const float* bn1_w     = (const float*)d_in[16];
    const float* bn1_b     = (const float*)d_in[17];
    const float* bn2_w     = (const float*)d_in[18];
    const float* bn2_b     = (const float*)d_in[19];
    const float* bn3_w     = (const float*)d_in[20];
    const float* bn3_b     = (const float*)d_in[21];
    const float* W1        = (const float*)d_in[22];
    const float* b1        = (const float*)d_in[23];
    const float* W2        = (const float*)d_in[24];
    const float* b2        = (const float*)d_in[25];
    const int*   edge_index= (const int*)d_in[26];

    const int N = in_sizes[0] / HH;
    const int E = in_sizes[1] / HH;
    const int G = in_sizes[2] / HH;
    const int PER = N / G;
    const int* src = edge_index;
    const int* dst = edge_index + E;
    float* outp = (float*)d_out;

    // symbol addresses
    u16 *wM0z_h,*wM0z_l,*wM0c_h,*wM0c_l,*wM0d_h,*wM0d_l,*wee_h,*wee_l;
    u16 *wM1_h,*wM1_l,*wM2_h,*wM2_l,*wM3_h,*wM3_l,*wU1_h,*wU1_l,*wU2_h,*wU2_l;
    u16 *wQKV_h,*wQKV_l,*wWo_h,*wWo_l,*wW1_h,*wW1_l,*wW2_h,*wW2_l,*wC_h,*wC_l,*wG_h,*wG_l;
    u16 *z_h,*z_l,*m0h,*m0l,*m1h,*m1l,*agh,*agl,*oh,*ol,*outh,*outl,*mlp1h,*mlp1l;
    float *cvec,*GDp,*zD,*zS,*t1,*h1,*qkv,*t2,*h2,*outf,*out2;
    unsigned *aggenc;
    SYMADDR(wM0z_h,g_wM0z_h); SYMADDR(wM0z_l,g_wM0z_l);
    SYMADDR(wM0c_h,g_wM0c_h); SYMADDR(wM0c_l,g_wM0c_l);
    SYMADDR(wM0d_h,g_wM0d_h); SYMADDR(wM0d_l,g_wM0d_l);
    SYMADDR(wee_h,g_wee_h);   SYMADDR(wee_l,g_wee_l);
    SYMADDR(wM1_h,g_wM1_h);   SYMADDR(wM1_l,g_wM1_l);
    SYMADDR(wM2_h,g_wM2_h);   SYMADDR(wM2_l,g_wM2_l);
    SYMADDR(wM3_h,g_wM3_h);   SYMADDR(wM3_l,g_wM3_l);
    SYMADDR(wU1_h,g_wU1_h);   SYMADDR(wU1_l,g_wU1_l);
    SYMADDR(wU2_h,g_wU2_h);   SYMADDR(wU2_l,g_wU2_l);
    SYMADDR(wQKV_h,g_wQKV_h); SYMADDR(wQKV_l,g_wQKV_l);
    SYMADDR(wWo_h,g_wWo_h);   SYMADDR(wWo_l,g_wWo_l);
    SYMADDR(wW1_h,g_wW1_h);   SYMADDR(wW1_l,g_wW1_l);
    SYMADDR(wW2_h,g_wW2_h);   SYMADDR(wW2_l,g_wW2_l);
    SYMADDR(wC_h,g_wC_h);     SYMADDR(wC_l,g_wC_l);
    SYMADDR(wG_h,g_wG_h);     SYMADDR(wG_l,g_wG_l);
    SYMADDR(z_h,g_z_h);       SYMADDR(z_l,g_z_l);
    SYMADDR(m0h,g_m0h); SYMADDR(m0l,g_m0l); SYMADDR(m1h,g_m1h); SYMADDR(m1l,g_m1l);
    SYMADDR(agh,g_agh); SYMADDR(agl,g_agl); SYMADDR(oh,g_oh); SYMADDR(ol,g_ol);
    SYMADDR(outh,g_outh); SYMADDR(outl,g_outl); SYMADDR(mlp1h,g_mlp1h); SYMADDR(mlp1l,g_mlp1l);
    SYMADDR(cvec,g_cvec); SYMADDR(GDp,g_GD); SYMADDR(zD,g_zD); SYMADDR(zS,g_zS);
    SYMADDR(t1,g_t1); SYMADDR(h1,g_h1); SYMADDR(qkv,g_qkv); SYMADDR(t2,g_t2);
    SYMADDR(h2,g_h2); SYMADDR(outf,g_out); SYMADDR(out2,g_out2);
    SYMADDR(aggenc,g_aggenc);

    // ---- weight prep: split to bf16 hi/lo ---------------------------------
    #define SPLIT(srcp, hp, lp, n) split_arr_k<<<((n)+255)/256, 256>>>(srcp, hp, lp, n)
    SPLIT(M0,                     wM0z_h, wM0z_l, 4*HH*HH);
    SPLIT(M0 + (size_t)4*HH*HH,   wM0c_h, wM0c_l, HH*HH);
    SPLIT(M0 + (size_t)5*HH*HH,   wM0d_h, wM0d_l, HH*HH);
    SPLIT(W_ee,                   wee_h,  wee_l,  HH*HH);
    SPLIT(M1, wM1_h, wM1_l, HH*HH);
    SPLIT(M2, wM2_h, wM2_l, HH*HH);
    SPLIT(M3, wM3_h, wM3_l, HH*HH);
    SPLIT(U1, wU1_h, wU1_l, 2*HH*HH);
    SPLIT(U2, wU2_h, wU2_l, HH*HH);
    SPLIT(Wqkv, wQKV_h, wQKV_l, 3*HH*HH);
    SPLIT(Wo, wWo_h, wWo_l, HH*HH);
    SPLIT(W1, wW1_h, wW1_l, 2*HH*HH);
    SPLIT(W2, wW2_h, wW2_l, 2*HH*HH);
    SPLIT(graph_fts, wG_h, wG_l, G*HH);
    cvec_k<<<1, HH>>>(b_ee, M0);
    split_z_k<<<(N*256 + 255)/256, 256>>>(node_fts, hidden, N*256);
    agg_init_k<<<(N*HH + 255)/256, 256>>>(N*HH);

    // ---- C = W_ee @ M0c (split out); GD = graph_fts @ M0d (fp32 out) ------
    run_gemm<1,0,false,false,false,false>(wee_h, wee_l, HH, wM0c_h, wM0c_l, HH,
        nullptr, wC_h, wC_l, nullptr, nullptr, nullptr, nullptr,
        nullptr, nullptr, nullptr, nullptr, nullptr, HH, HH, HH, PER);
    run_gemm<0,0,false,false,false,false>(wG_h, wG_l, HH, wM0d_h, wM0d_l, HH,
        GDp, nullptr, nullptr, nullptr, nullptr, nullptr, nullptr,
        nullptr, nullptr, nullptr, nullptr, nullptr, G, HH, HH, PER);

    // ---- zD = z @ M0[0:2H], zS = z @ M0[2H:4H]  (K=256, fp32 out) ---------
    run_gemm<0,0,false,false,false,false>(z_h, z_l, 256, wM0z_h, wM0z_l, HH,
        zD, nullptr, nullptr, nullptr, nullptr, nullptr, nullptr,
        nullptr, nullptr, nullptr, nullptr, nullptr, N, HH, 256, PER);
    run_gemm<0,0,false,false,false,false>(z_h, z_l, 256, wM0z_h + (size_t)2*HH*HH, wM0z_l + (size_t)2*HH*HH, HH,
        zS, nullptr, nullptr, nullptr, nullptr, nullptr, nullptr,
        nullptr, nullptr, nullptr, nullptr, nullptr, N, HH, 256, PER);

    // ---- e0 GEMM + fused gather: m0 = split(leaky(ea@C + zD[d]+zS[s]+GD[g]+cvec))
    run_gemm<3,0,false,false,false,true>(edge_attr, nullptr, HH, wC_h, wC_l, HH,
        nullptr, m0h, m0l, nullptr, nullptr, src, dst,
        zD, zS, GDp, cvec, nullptr, E, HH, HH, PER);

    // ---- M1, M2 (split+leaky out), M3 (fused segment-max atomics) ---------
    run_gemm<1,2,false,false,false,false>(m0h, m0l, HH, wM1_h, wM1_l, HH,
        nullptr, m1h, m1l, nullptr, nullptr, nullptr, nullptr,
        nullptr, nullptr, nullptr, nullptr, nullptr, E, HH, HH, PER);
    run_gemm<1,2,false,false,false,false>(m1h, m1l, HH, wM2_h, wM2_l, HH,
        nullptr, m0h, m0l, nullptr, nullptr, nullptr, nullptr,
        nullptr, nullptr, nullptr, nullptr, nullptr, E, HH, HH, PER);
    run_gemm<2,0,false,false,false,false>(m0h, m0l, HH, wM3_h, wM3_l, HH,
        nullptr, nullptr, nullptr, nullptr, nullptr, nullptr, dst,
        nullptr, nullptr, nullptr, nullptr, aggenc, E, HH, HH, PER);
    agg_decode_k<<<(N*HH + 255)/256, 256>>>(N*HH);

    // ---- h1 = BN1(z@U1 + agg@U2 + node_fts) -------------------------------
    run_gemm<0,0,false,false,false,false>(z_h, z_l, 256, wU1_h, wU1_l, HH,
        t1, nullptr, nullptr, nullptr, nullptr, nullptr, nullptr,
        nullptr, nullptr, nullptr, nullptr, nullptr, N, HH, 256, PER);
    run_gemm<0,0,false,true,true,false>(agh, agl, HH, wU2_h, wU2_l, HH,
        t1, nullptr, nullptr, nullptr, node_fts, nullptr, nullptr,
        nullptr, nullptr, nullptr, nullptr, nullptr, N, HH, HH, PER);
    {
        bn_stats1_k<<<256, 128>>>(t1, N/256);
        bn_stats2_k<<<1, 128>>>(256, 1.0f/(float)N);
        bn_apply_k<<<(N*HH + 255)/256, 256>>>(t1, bn1_w, bn1_b, h1, N*HH);
    }

    // ---- attention --------------------------------------------------------
    run_gemm<0,0,true,false,false,false>(z_h, z_l, 256, wQKV_h, wQKV_l, 3*HH,
        qkv, nullptr, nullptr, bqkv, nullptr, nullptr, nullptr,
        nullptr, nullptr, nullptr, nullptr, nullptr, N, 3*HH, HH, PER);
    attn_k<<<dim3(G, 4), PER>>>(qkv, PER);
    run_gemm<0,0,true,false,true,false>(oh, ol, HH, wWo_h, wWo_l, HH,
        t2, nullptr, nullptr, bo, node_fts, nullptr, nullptr,
        nullptr, nullptr, nullptr, nullptr, nullptr, N, HH, HH, PER);
    {
        bn_stats1_k<<<256, 128>>>(t2, N/256);
        bn_stats2_k<<<1, 128>>>(256, 1.0f/(float)N);
        bn_apply_k<<<(N*HH + 255)/256, 256>>>(t2, bn2_w, bn2_b, h2, N*HH);
    }

    // ---- combine + MLP ----------------------------------------------------
    add_split_k<<<(N*HH + 255)/256, 256>>>(h1, h2, N*HH);
    run_gemm<1,1,true,false,false,false>(outh, outl, HH, wW1_h, wW1_l, 2*HH,
        nullptr, mlp1h, mlp1l, b1, nullptr, nullptr, nullptr,
        nullptr, nullptr, nullptr, nullptr, nullptr, N, 2*HH, HH, PER);
    run_gemm<0,0,true,false,true,false>(mlp1h, mlp1l, 2*HH, wW2_h, wW2_l, HH,
        out2, nullptr, nullptr, b2, outf, nullptr, nullptr,
        nullptr, nullptr, nullptr, nullptr, nullptr, N, HH, 2*HH, PER);

    // ---- BN3 -> output ----------------------------------------------------
    {
        bn_stats1_k<<<256, 128>>>(out2, N/256);
        bn_stats2_k<<<1, 128>>>(256, 1.0f/(float)N);
        bn_apply_k<<<(N*HH + 255)/256, 256>>>(out2, bn3_w, bn3_b, outp, N*HH);
    }
}